// round 13
// baseline (speedup 1.0000x reference)
#include <cuda_runtime.h>
#include <cuda_fp16.h>
#include <cstdint>

#define Bsz 4
#define Cch 256
#define Hh  64
#define Ww  64
#define Oo  256
#define Kt  9
#define Md  (Bsz*Hh*Ww)   // 16384
#define Kd  (Cch*Kt)      // 2304

// ---------------- scratch ----------------
__device__ __half g_nhwcH[(size_t)Bsz*Hh*Ww*Cch];   // fp16 NHWC
__device__ float g_off[(size_t)Bsz*18*Hh*Ww];
__device__ __half g_B[(size_t)Oo*Kd];
__device__ __half g_Boff[(size_t)32*Kd];
__device__ float g_bias2[Oo];

// ---------------- helpers ----------------
__device__ __forceinline__ uint32_t smem_u32(const void* p) {
    uint32_t a;
    asm("{ .reg .u64 t; cvta.to.shared.u64 t, %1; cvt.u32.u64 %0, t; }" : "=r"(a) : "l"(p));
    return a;
}
__device__ __forceinline__ void cpa16(uint32_t s, const void* g) {
    asm volatile("cp.async.cg.shared.global [%0], [%1], 16;" :: "r"(s), "l"(g));
}
__device__ __forceinline__ void cpa16z(uint32_t s, const void* g, int valid) {
    asm volatile("cp.async.cg.shared.global [%0], [%1], 16, %2;"
                 :: "r"(s), "l"(g), "r"(valid ? 16 : 0));
}
#define LDMX4(r, addr) \
    asm volatile("ldmatrix.sync.aligned.m8n8.x4.shared.b16 {%0,%1,%2,%3}, [%4];" \
        : "=r"((r)[0]), "=r"((r)[1]), "=r"((r)[2]), "=r"((r)[3]) : "r"(addr))
#define MMA16816(d, a, b0, b1) \
    asm volatile("mma.sync.aligned.m16n8k16.row.col.f32.f16.f16.f32 " \
        "{%0,%1,%2,%3}, {%4,%5,%6,%7}, {%8,%9}, {%0,%1,%2,%3};" \
        : "+f"((d)[0]), "+f"((d)[1]), "+f"((d)[2]), "+f"((d)[3]) \
        : "r"((a)[0]), "r"((a)[1]), "r"((a)[2]), "r"((a)[3]), "r"(b0), "r"(b1))

// ---------------- 1) transpose to fp16 NHWC + weight prep ----------------
__global__ void k_transpose_prep(const float* __restrict__ in,
                                 const float* __restrict__ w,
                                 const float* __restrict__ w_off,
                                 const float* __restrict__ bias,
                                 const float* __restrict__ gamma,
                                 const float* __restrict__ beta,
                                 const float* __restrict__ mean,
                                 const float* __restrict__ var) {
    if (blockIdx.y == 8) {
        int o = blockIdx.z;
        int tid = threadIdx.y * 32 + threadIdx.x;
        float inv = gamma[o] * rsqrtf(var[o] + 1e-5f);
        int kd0 = blockIdx.x * (Kd/2);
        for (int i = tid; i < Kd/2; i += 256) {
            int kd = kd0 + i;
            int tap = kd >> 8, c = kd & 255;
            g_B[(size_t)o*Kd + kd] = __float2half_rn(w[((size_t)(o*Cch + c))*9 + tap] * inv);
        }
        if (tid == 0 && blockIdx.x == 0)
            g_bias2[o] = bias[o]*inv + beta[o] - mean[o]*inv;
        return;
    }
    if (blockIdx.y == 9) {
        int j = blockIdx.z;
        if (j >= 32 || blockIdx.x != 0) return;
        int tid = threadIdx.y * 32 + threadIdx.x;
        for (int kd = tid; kd < Kd; kd += 256) {
            int tap = kd >> 8, c = kd & 255;
            __half v = __float2half_rn(0.f);
            if (j < 18) v = __float2half_rn(w_off[((size_t)(j*Cch + c))*9 + tap]);
            g_Boff[(size_t)j*Kd + kd] = v;
        }
        return;
    }
    __shared__ float t[32][33];
    int x0 = blockIdx.x * 32;
    int c0 = blockIdx.y * 32;
    int bh = blockIdx.z;
    int b = bh >> 6, y = bh & 63;
    #pragma unroll
    for (int i = threadIdx.y; i < 32; i += 8)
        t[i][threadIdx.x] = in[(((size_t)(b*Cch + c0 + i)*Hh + y)*Ww) + x0 + threadIdx.x];
    __syncthreads();
    #pragma unroll
    for (int i = threadIdx.y; i < 32; i += 8) {
        size_t o = (((size_t)(b*Hh + y)*Ww + x0 + i) << 8) + c0 + threadIdx.x;
        g_nhwcH[o] = __float2half_rn(t[threadIdx.x][i]);
    }
}

// ---------------- 2) offset conv as 1-term fp16 mma GEMM (256 thr) ----------------
#define KC2 32
#define NCH2 (Kd/KC2)        // 72
#define APL2 10240           // 128 rows x 80B
#define BSM2 2560            // 32 rows x 80B
#define STG2 (APL2 + BSM2)   // 12800
#define NSTG2 4

__global__ __launch_bounds__(256, 1) void k_offset_gemm(const float* __restrict__ b_off) {
    extern __shared__ char dsm[];
    const uint32_t sbase = smem_u32(dsm);
    const int tid = threadIdx.x, lid = tid & 31, wid = tid >> 5;   // 8 warps
    const int m0 = blockIdx.x * 128;
    const int b = m0 >> 12, y0 = (m0 >> 6) & 63;

    float acc[4][4];
    #pragma unroll
    for (int nt = 0; nt < 4; nt++)
        #pragma unroll
        for (int j = 0; j < 4; j++) acc[nt][j] = 0.f;

    const uint32_t a_off = (uint32_t)((wid*16 + (lid & 15)) * 80 + (lid >> 4) * 16);
    const uint32_t b_offs = (uint32_t)(((lid & 7) + ((lid >> 4) & 1)*8) * 80
                                       + ((lid >> 3) & 1) * 16);

    auto load = [&](int c, int p) {
        uint32_t sb = sbase + p * STG2;
        int tap = c >> 3;
        int ky = tap / 3 - 1, kx = tap % 3 - 1;
        int c0 = (c & 7) * 32;
        #pragma unroll
        for (int i = 0; i < 2; i++) {
            int idx = tid + i*256;
            int r   = idx >> 2;
            int j   = idx & 3;
            int ry = y0 + (r >> 6) + ky;
            int rx = (r & 63) + kx;
            int valid = ((unsigned)ry < 64u) && ((unsigned)rx < 64u);
            int ryc = min(max(ry, 0), 63), rxc = min(max(rx, 0), 63);
            const __half* src = g_nhwcH + (((size_t)(b*Hh + ryc)*Ww + rxc) << 8) + c0 + j*8;
            cpa16z(sb + r*80 + j*16, src, valid);
        }
        if (tid < 128) {
            int rr = tid >> 2;
            int j  = tid & 3;
            cpa16(sb + APL2 + rr*80 + j*16, g_Boff + (size_t)rr*Kd + tap*Cch + c0 + j*8);
        }
        asm volatile("cp.async.commit_group;");
    };

    load(0, 0);
    load(1, 1);
    load(2, 2);

    for (int c = 0; c < NCH2; c++) {
        int p = c & 3;
        if (c + 3 < NCH2) {
            load(c + 3, (c + 3) & 3);
            asm volatile("cp.async.wait_group 3;" ::: "memory");
        } else if (c + 2 < NCH2) {
            asm volatile("cp.async.wait_group 2;" ::: "memory");
        } else if (c + 1 < NCH2) {
            asm volatile("cp.async.wait_group 1;" ::: "memory");
        } else {
            asm volatile("cp.async.wait_group 0;" ::: "memory");
        }
        __syncthreads();

        uint32_t sb = sbase + p * STG2;
        #pragma unroll
        for (int kh = 0; kh < 2; kh++) {
            uint32_t ah[4];
            LDMX4(ah, sb + a_off + kh*32);
            #pragma unroll
            for (int tp = 0; tp < 2; tp++) {
                uint32_t bb[4];
                LDMX4(bb, sb + APL2 + b_offs + tp*(16*80) + kh*32);
                #pragma unroll
                for (int q = 0; q < 2; q++)
                    MMA16816(acc[tp*2 + q], ah, bb[2*q], bb[2*q+1]);
            }
        }
        __syncthreads();
    }

    {
        int mA = m0 + wid*16 + (lid >> 2);
        int mB = mA + 8;
        int pA = mA & 4095, pB = mB & 4095;
        #pragma unroll
        for (int nt = 0; nt < 4; nt++) {
            int j0 = nt*8 + (lid & 3)*2;
            float* d = acc[nt];
            if (j0 < 18) {
                float bv = b_off[j0];
                g_off[((size_t)(b*18 + j0) << 12) + pA] = d[0] + bv;
                g_off[((size_t)(b*18 + j0) << 12) + pB] = d[2] + bv;
            }
            if (j0 + 1 < 18) {
                float bv = b_off[j0 + 1];
                g_off[((size_t)(b*18 + j0 + 1) << 12) + pA] = d[1] + bv;
                g_off[((size_t)(b*18 + j0 + 1) << 12) + pB] = d[3] + bv;
            }
        }
    }
}

// ---------------- 3) fused sample + fp16 mma GEMM, KC=64 ----------------
#define KC 64
#define NCH (Kd/KC)          // 36
#define PITCH 144            // 128B data + 16B pad per row
#define APL (128*PITCH)      // 18432, double buffered
#define BPL (256*PITCH)      // 36864
#define BBASE (2*APL)        // 36864
#define NSTGB 3
#define SMEMSZ (2*APL + NSTGB*BPL)   // 147456

__global__ __launch_bounds__(256, 1) void k_gemm_fused(float* __restrict__ out) {
    extern __shared__ char dsm[];
    const uint32_t sbase = smem_u32(dsm);
    char* dsmp = dsm;
    const int tid = threadIdx.x, lid = tid & 31, wid = tid >> 5;
    const int warpM = wid & 1, warpN = wid >> 1;   // 2 x 4, warp tile 64x64
    const int m0 = blockIdx.x * 128;
    const int bb = m0 >> 12;
    const int pbase = m0 & 4095;

    float acc[4][8][4];
    #pragma unroll
    for (int mt = 0; mt < 4; mt++)
        #pragma unroll
        for (int nt = 0; nt < 8; nt++)
            #pragma unroll
            for (int j = 0; j < 4; j++) acc[mt][nt][j] = 0.f;

    const uint32_t a_off = (uint32_t)((warpM*64 + (lid & 15)) * PITCH + (lid >> 4) * 16);
    const uint32_t bm_off = (uint32_t)((warpN*64 + (lid & 7) + ((lid >> 4) & 1)*8) * PITCH
                                       + ((lid >> 3) & 1) * 16);

    // gather: one row per thread (2 lanes per row), 4 x 16B slices per thread
    float gw[4];
    uint32_t gb[4];
    const int grow = wid*16 + (lid >> 1);
    const int half = lid & 1;
    const uint32_t hoff = (uint32_t)(half * 64);

    auto calc_tap = [&](int tap) {
        int p = pbase + grow;
        int y = (p >> 6) & 63, x = p & 63;
        float dy = g_off[((size_t)(bb*18 + 2*tap) << 12) + p];
        float dx = g_off[((size_t)(bb*18 + 2*tap + 1) << 12) + p];
        float py = (float)(y - 1 + tap/3) + dy;
        float px = (float)(x - 1 + tap%3) + dx;
        float y0f = floorf(py), x0f = floorf(px);
        float ly = py - y0f, lx = px - x0f;
        int y0 = (int)y0f, x0i = (int)x0f;
        int y1 = y0 + 1,  x1 = x0i + 1;
        float vy0 = (y0  >= 0 && y0  < 64) ? 1.f : 0.f;
        float vy1 = (y1  >= 0 && y1  < 64) ? 1.f : 0.f;
        float vx0 = (x0i >= 0 && x0i < 64) ? 1.f : 0.f;
        float vx1 = (x1  >= 0 && x1  < 64) ? 1.f : 0.f;
        gw[0] = (1.f-ly)*(1.f-lx)*vy0*vx0;
        gw[1] = (1.f-ly)*lx      *vy0*vx1;
        gw[2] = ly      *(1.f-lx)*vy1*vx0;
        gw[3] = ly      *lx      *vy1*vx1;
        int y0c = min(max(y0, 0), 63), y1c = min(max(y1, 0), 63);
        int x0c = min(max(x0i,0), 63), x1c = min(max(x1, 0), 63);
        uint32_t rowb = (uint32_t)(bb << 12);
        gb[0] = (rowb + (y0c << 6) + x0c) << 9;
        gb[1] = (rowb + (y0c << 6) + x1c) << 9;
        gb[2] = (rowb + (y1c << 6) + x0c) << 9;
        gb[3] = (rowb + (y1c << 6) + x1c) << 9;
    };

    const char* nb = (const char*)g_nhwcH;

    // gather slices jbase, jbase+1 (each 16B x 4 corners)
    auto gather2 = [&](int jbase, uint32_t c0bytes, uint4 cd[2][4]) {
        #pragma unroll
        for (int jj = 0; jj < 2; jj++) {
            uint32_t off = c0bytes + hoff + (uint32_t)((jbase + jj) * 16);
            cd[jj][0] = *(const uint4*)(nb + gb[0] + off);
            cd[jj][1] = *(const uint4*)(nb + gb[1] + off);
            cd[jj][2] = *(const uint4*)(nb + gb[2] + off);
            cd[jj][3] = *(const uint4*)(nb + gb[3] + off);
        }
    };

    auto combine2 = [&](int jbase, uint4 cd[2][4], uint32_t abuf) {
        #pragma unroll
        for (int jj = 0; jj < 2; jj++) {
            uint4 pk;
            uint32_t* po = (uint32_t*)&pk;
            #pragma unroll
            for (int wds = 0; wds < 4; wds++) {
                float2 f0 = __half22float2(((const __half2*)&cd[jj][0])[wds]);
                float2 f1 = __half22float2(((const __half2*)&cd[jj][1])[wds]);
                float2 f2 = __half22float2(((const __half2*)&cd[jj][2])[wds]);
                float2 f3 = __half22float2(((const __half2*)&cd[jj][3])[wds]);
                float rx = gw[0]*f0.x + gw[1]*f1.x + gw[2]*f2.x + gw[3]*f3.x;
                float ry = gw[0]*f0.y + gw[1]*f1.y + gw[2]*f2.y + gw[3]*f3.y;
                __half2 h = __floats2half2_rn(rx, ry);
                po[wds] = *(uint32_t*)&h;
            }
            *(uint4*)(dsmp + abuf + grow*PITCH + hoff + (jbase + jj)*16) = pk;
        }
    };

    auto loadB = [&](int c, int p) {
        uint32_t sb = sbase + BBASE + p * BPL;
        size_t kOff = (size_t)c * KC;
        #pragma unroll
        for (int i = 0; i < 8; i++) {
            int idx = tid + i*256;
            int rr = idx >> 3;
            int j  = idx & 7;
            cpa16(sb + rr*PITCH + j*16, g_B + (size_t)rr*Kd + kOff + j*8);
        }
        asm volatile("cp.async.commit_group;");
    };

    // prologue: A(0) into stage 0, B(0..1)
    calc_tap(0);
    {
        uint4 cd[2][4];
        gather2(0, 0, cd); combine2(0, cd, 0);
        gather2(2, 0, cd); combine2(2, cd, 0);
    }
    loadB(0, 0);
    loadB(1, 1);

    for (int c = 0; c < NCH; c++) {
        if (c + 1 < NCH) {
            asm volatile("cp.async.wait_group 1;" ::: "memory");
        } else {
            asm volatile("cp.async.wait_group 0;" ::: "memory");
        }
        __syncthreads();

        const int prep = (c + 1 < NCH);
        const int cn = c + 1;
        if (prep && ((cn & 3) == 0)) calc_tap(cn >> 2);
        const uint32_t c0bytes = (uint32_t)((cn & 3) * 128);
        const uint32_t abuf_n = (uint32_t)((cn & 1) * APL);

        uint32_t sbB = sbase + BBASE + (c % 3) * BPL;
        uint32_t sbA = sbase + (c & 1) * APL;

        uint4 cd01[2][4], cd23[2][4];
        if (prep) gather2(0, c0bytes, cd01);

        // kh = 0, 1
        #pragma unroll
        for (int kh = 0; kh < 2; kh++) {
            uint32_t ah[4][4];
            #pragma unroll
            for (int mt = 0; mt < 4; mt++)
                LDMX4(ah[mt], sbA + a_off + mt*(16*PITCH) + kh*32);
            #pragma unroll
            for (int tp = 0; tp < 4; tp++) {
                uint32_t bfr[4];
                LDMX4(bfr, sbB + bm_off + tp*(16*PITCH) + kh*32);
                #pragma unroll
                for (int q = 0; q < 2; q++) {
                    int nt = tp*2 + q;
                    #pragma unroll
                    for (int mt = 0; mt < 4; mt++)
                        MMA16816(acc[mt][nt], ah[mt], bfr[2*q], bfr[2*q+1]);
                }
            }
        }
        if (prep) { combine2(0, cd01, abuf_n); gather2(2, c0bytes, cd23); }
        // kh = 2, 3
        #pragma unroll
        for (int kh = 2; kh < 4; kh++) {
            uint32_t ah[4][4];
            #pragma unroll
            for (int mt = 0; mt < 4; mt++)
                LDMX4(ah[mt], sbA + a_off + mt*(16*PITCH) + kh*32);
            #pragma unroll
            for (int tp = 0; tp < 4; tp++) {
                uint32_t bfr[4];
                LDMX4(bfr, sbB + bm_off + tp*(16*PITCH) + kh*32);
                #pragma unroll
                for (int q = 0; q < 2; q++) {
                    int nt = tp*2 + q;
                    #pragma unroll
                    for (int mt = 0; mt < 4; mt++)
                        MMA16816(acc[mt][nt], ah[mt], bfr[2*q], bfr[2*q+1]);
                }
            }
        }
        if (prep) combine2(2, cd23, abuf_n);
        if (c + 2 < NCH) loadB(c + 2, (c + 2) % 3);
    }

    // epilogue: bias + relu, NCHW stores
    #pragma unroll
    for (int mt = 0; mt < 4; mt++) {
        int mA = m0 + warpM*64 + mt*16 + (lid >> 2);
        int mB = mA + 8;
        int bA = mA >> 12, bB = mB >> 12;
        int pA = mA & 4095, pB = mB & 4095;
        #pragma unroll
        for (int nt = 0; nt < 8; nt++) {
            int o = warpN*64 + nt*8 + (lid & 3)*2;
            float bv0 = g_bias2[o], bv1 = g_bias2[o + 1];
            float* d = acc[mt][nt];
            out[((size_t)bA << 20) + ((size_t)o << 12)     + pA] = fmaxf(d[0] + bv0, 0.f);
            out[((size_t)bA << 20) + ((size_t)(o+1) << 12) + pA] = fmaxf(d[1] + bv1, 0.f);
            out[((size_t)bB << 20) + ((size_t)o << 12)     + pB] = fmaxf(d[2] + bv0, 0.f);
            out[((size_t)bB << 20) + ((size_t)(o+1) << 12) + pB] = fmaxf(d[3] + bv1, 0.f);
        }
    }
}

// ---------------- launch ----------------
extern "C" void kernel_launch(void* const* d_in, const int* in_sizes, int n_in,
                              void* d_out, int out_size) {
    const float* input  = (const float*)d_in[0];
    const float* w_off  = (const float*)d_in[1];
    const float* b_off  = (const float*)d_in[2];
    const float* weight = (const float*)d_in[3];
    const float* bias   = (const float*)d_in[4];
    const float* gamma  = (const float*)d_in[5];
    const float* beta   = (const float*)d_in[6];
    const float* mean   = (const float*)d_in[7];
    const float* var    = (const float*)d_in[8];
    float* out = (float*)d_out;

    cudaFuncSetAttribute(k_gemm_fused, cudaFuncAttributeMaxDynamicSharedMemorySize, SMEMSZ);
    cudaFuncSetAttribute(k_offset_gemm, cudaFuncAttributeMaxDynamicSharedMemorySize, NSTG2*STG2);

    k_transpose_prep<<<dim3(2, 10, 256), dim3(32, 8)>>>(input, weight, w_off, bias, gamma, beta, mean, var);
    k_offset_gemm<<<Md/128, 256, NSTG2*STG2>>>(b_off);
    k_gemm_fused<<<Md/128, 256, SMEMSZ>>>(out);
}

// round 14
// speedup vs baseline: 1.0827x; 1.0827x over previous
#include <cuda_runtime.h>
#include <cuda_fp16.h>
#include <cstdint>

#define Bsz 4
#define Cch 256
#define Hh  64
#define Ww  64
#define Oo  256
#define Kt  9
#define Md  (Bsz*Hh*Ww)   // 16384
#define Kd  (Cch*Kt)      // 2304

// ---------------- scratch ----------------
__device__ __half g_nhwcH[(size_t)Bsz*Hh*Ww*Cch];   // fp16 NHWC
__device__ float g_off[(size_t)Bsz*18*Hh*Ww];
__device__ __half g_B[(size_t)Oo*Kd];
__device__ __half g_Boff[(size_t)32*Kd];
__device__ float g_bias2[Oo];

// ---------------- helpers ----------------
__device__ __forceinline__ uint32_t smem_u32(const void* p) {
    uint32_t a;
    asm("{ .reg .u64 t; cvta.to.shared.u64 t, %1; cvt.u32.u64 %0, t; }" : "=r"(a) : "l"(p));
    return a;
}
__device__ __forceinline__ void cpa16(uint32_t s, const void* g) {
    asm volatile("cp.async.cg.shared.global [%0], [%1], 16;" :: "r"(s), "l"(g));
}
__device__ __forceinline__ void cpa16z(uint32_t s, const void* g, int valid) {
    asm volatile("cp.async.cg.shared.global [%0], [%1], 16, %2;"
                 :: "r"(s), "l"(g), "r"(valid ? 16 : 0));
}
#define LDMX4(r, addr) \
    asm volatile("ldmatrix.sync.aligned.m8n8.x4.shared.b16 {%0,%1,%2,%3}, [%4];" \
        : "=r"((r)[0]), "=r"((r)[1]), "=r"((r)[2]), "=r"((r)[3]) : "r"(addr))
#define MMA16816(d, a, b0, b1) \
    asm volatile("mma.sync.aligned.m16n8k16.row.col.f32.f16.f16.f32 " \
        "{%0,%1,%2,%3}, {%4,%5,%6,%7}, {%8,%9}, {%0,%1,%2,%3};" \
        : "+f"((d)[0]), "+f"((d)[1]), "+f"((d)[2]), "+f"((d)[3]) \
        : "r"((a)[0]), "r"((a)[1]), "r"((a)[2]), "r"((a)[3]), "r"(b0), "r"(b1))

// ---------------- 1) transpose to fp16 NHWC + weight prep ----------------
// grid (2, 6, 256): y<4 -> transpose c-quarter, y==4 -> main weight prep, y==5 -> offset weights
__global__ void k_transpose_prep(const float* __restrict__ in,
                                 const float* __restrict__ w,
                                 const float* __restrict__ w_off,
                                 const float* __restrict__ bias,
                                 const float* __restrict__ gamma,
                                 const float* __restrict__ beta,
                                 const float* __restrict__ mean,
                                 const float* __restrict__ var) {
    const int tx = threadIdx.x, ty = threadIdx.y;
    if (blockIdx.y == 4) {
        int o = blockIdx.z;
        int tid = ty * 32 + tx;
        float inv = gamma[o] * rsqrtf(var[o] + 1e-5f);
        int kd0 = blockIdx.x * (Kd/2);
        for (int i = tid; i < Kd/2; i += 256) {
            int kd = kd0 + i;
            int tap = kd >> 8, c = kd & 255;
            g_B[(size_t)o*Kd + kd] = __float2half_rn(w[((size_t)(o*Cch + c))*9 + tap] * inv);
        }
        if (tid == 0 && blockIdx.x == 0)
            g_bias2[o] = bias[o]*inv + beta[o] - mean[o]*inv;
        return;
    }
    if (blockIdx.y == 5) {
        int j = blockIdx.z;
        if (j >= 32 || blockIdx.x != 0) return;
        int tid = ty * 32 + tx;
        for (int kd = tid; kd < Kd; kd += 256) {
            int tap = kd >> 8, c = kd & 255;
            __half v = __float2half_rn(0.f);
            if (j < 18) v = __float2half_rn(w_off[((size_t)(j*Cch + c))*9 + tap]);
            g_Boff[(size_t)j*Kd + kd] = v;
        }
        return;
    }
    // transpose: 64 channels x 32 x per block
    __shared__ float t[64][33];
    const int x0 = blockIdx.x * 32;
    const int c0 = blockIdx.y * 64;
    const int bh = blockIdx.z;
    const int b = bh >> 6, y = bh & 63;
    const float* ib = in + (((size_t)(b*Cch + c0))*Hh + y)*Ww + x0;
    #pragma unroll
    for (int i = 0; i < 8; i++) {
        int r = ty + i*8;
        t[r][tx] = ib[(size_t)r*Hh*Ww + tx];
    }
    __syncthreads();
    __half* ob = g_nhwcH + (((size_t)(b*Hh + y)*Ww + x0) << 8) + c0;
    #pragma unroll
    for (int i = 0; i < 4; i++) {
        int x = ty + i*8;
        __half2 h = __floats2half2_rn(t[2*tx][x], t[2*tx + 1][x]);
        *(__half2*)(ob + ((size_t)x << 8) + 2*tx) = h;
    }
}

// ---------------- 2) offset conv as 1-term fp16 mma GEMM (256 thr) ----------------
#define KC2 32
#define NCH2 (Kd/KC2)        // 72
#define APL2 10240           // 128 rows x 80B
#define BSM2 2560            // 32 rows x 80B
#define STG2 (APL2 + BSM2)   // 12800
#define NSTG2 4

__global__ __launch_bounds__(256, 1) void k_offset_gemm(const float* __restrict__ b_off) {
    extern __shared__ char dsm[];
    const uint32_t sbase = smem_u32(dsm);
    const int tid = threadIdx.x, lid = tid & 31, wid = tid >> 5;   // 8 warps
    const int m0 = blockIdx.x * 128;
    const int b = m0 >> 12, y0 = (m0 >> 6) & 63;

    float acc[4][4];
    #pragma unroll
    for (int nt = 0; nt < 4; nt++)
        #pragma unroll
        for (int j = 0; j < 4; j++) acc[nt][j] = 0.f;

    const uint32_t a_off = (uint32_t)((wid*16 + (lid & 15)) * 80 + (lid >> 4) * 16);
    const uint32_t b_offs = (uint32_t)(((lid & 7) + ((lid >> 4) & 1)*8) * 80
                                       + ((lid >> 3) & 1) * 16);

    auto load = [&](int c, int p) {
        uint32_t sb = sbase + p * STG2;
        int tap = c >> 3;
        int ky = tap / 3 - 1, kx = tap % 3 - 1;
        int c0 = (c & 7) * 32;
        #pragma unroll
        for (int i = 0; i < 2; i++) {
            int idx = tid + i*256;
            int r   = idx >> 2;
            int j   = idx & 3;
            int ry = y0 + (r >> 6) + ky;
            int rx = (r & 63) + kx;
            int valid = ((unsigned)ry < 64u) && ((unsigned)rx < 64u);
            int ryc = min(max(ry, 0), 63), rxc = min(max(rx, 0), 63);
            const __half* src = g_nhwcH + (((size_t)(b*Hh + ryc)*Ww + rxc) << 8) + c0 + j*8;
            cpa16z(sb + r*80 + j*16, src, valid);
        }
        if (tid < 128) {
            int rr = tid >> 2;
            int j  = tid & 3;
            cpa16(sb + APL2 + rr*80 + j*16, g_Boff + (size_t)rr*Kd + tap*Cch + c0 + j*8);
        }
        asm volatile("cp.async.commit_group;");
    };

    load(0, 0);
    load(1, 1);
    load(2, 2);

    for (int c = 0; c < NCH2; c++) {
        int p = c & 3;
        if (c + 3 < NCH2) {
            load(c + 3, (c + 3) & 3);
            asm volatile("cp.async.wait_group 3;" ::: "memory");
        } else if (c + 2 < NCH2) {
            asm volatile("cp.async.wait_group 2;" ::: "memory");
        } else if (c + 1 < NCH2) {
            asm volatile("cp.async.wait_group 1;" ::: "memory");
        } else {
            asm volatile("cp.async.wait_group 0;" ::: "memory");
        }
        __syncthreads();

        uint32_t sb = sbase + p * STG2;
        #pragma unroll
        for (int kh = 0; kh < 2; kh++) {
            uint32_t ah[4];
            LDMX4(ah, sb + a_off + kh*32);
            #pragma unroll
            for (int tp = 0; tp < 2; tp++) {
                uint32_t bb[4];
                LDMX4(bb, sb + APL2 + b_offs + tp*(16*80) + kh*32);
                #pragma unroll
                for (int q = 0; q < 2; q++)
                    MMA16816(acc[tp*2 + q], ah, bb[2*q], bb[2*q+1]);
            }
        }
        __syncthreads();
    }

    {
        int mA = m0 + wid*16 + (lid >> 2);
        int mB = mA + 8;
        int pA = mA & 4095, pB = mB & 4095;
        #pragma unroll
        for (int nt = 0; nt < 4; nt++) {
            int j0 = nt*8 + (lid & 3)*2;
            float* d = acc[nt];
            if (j0 < 18) {
                float bv = b_off[j0];
                g_off[((size_t)(b*18 + j0) << 12) + pA] = d[0] + bv;
                g_off[((size_t)(b*18 + j0) << 12) + pB] = d[2] + bv;
            }
            if (j0 + 1 < 18) {
                float bv = b_off[j0 + 1];
                g_off[((size_t)(b*18 + j0 + 1) << 12) + pA] = d[1] + bv;
                g_off[((size_t)(b*18 + j0 + 1) << 12) + pB] = d[3] + bv;
            }
        }
    }
}

// ---------------- 3) fused sample + fp16 mma GEMM (R12 config, KC=32) ----------------
#define KC 32
#define NCH (Kd/KC)          // 72
#define APL 10240            // A buffer (128 rows x 80B), double buffered
#define BPL 20480            // B stage (256 rows x 80B)
#define BBASE (2*APL)
#define NSTGB 4
#define SMEMSZ (2*APL + NSTGB*BPL)   // 102400

__global__ __launch_bounds__(256, 1) void k_gemm_fused(float* __restrict__ out) {
    extern __shared__ char dsm[];
    const uint32_t sbase = smem_u32(dsm);
    char* dsmp = dsm;
    const int tid = threadIdx.x, lid = tid & 31, wid = tid >> 5;
    const int warpM = wid & 1, warpN = wid >> 1;   // 2 x 4, warp tile 64x64
    const int m0 = blockIdx.x * 128;
    const int bb = m0 >> 12;
    const int pbase = m0 & 4095;

    float acc[4][8][4];
    #pragma unroll
    for (int mt = 0; mt < 4; mt++)
        #pragma unroll
        for (int nt = 0; nt < 8; nt++)
            #pragma unroll
            for (int j = 0; j < 4; j++) acc[mt][nt][j] = 0.f;

    const uint32_t a_off = (uint32_t)((warpM*64 + (lid & 15)) * 80 + (lid >> 4) * 16);
    const uint32_t bm_off = (uint32_t)((warpN*64 + (lid & 7) + ((lid >> 4) & 1)*8) * 80
                                       + ((lid >> 3) & 1) * 16);

    float gw[2][4];
    uint32_t gb[2][4];
    const int growl[2] = { wid*16 + (lid >> 2), wid*16 + 8 + (lid >> 2) };
    const uint32_t chb = (uint32_t)((lid & 3) * 16);

    auto calc_tap = [&](int tap) {
        #pragma unroll
        for (int it = 0; it < 2; it++) {
            int p = pbase + growl[it];
            int y = (p >> 6) & 63, x = p & 63;
            float dy = g_off[((size_t)(bb*18 + 2*tap) << 12) + p];
            float dx = g_off[((size_t)(bb*18 + 2*tap + 1) << 12) + p];
            float py = (float)(y - 1 + tap/3) + dy;
            float px = (float)(x - 1 + tap%3) + dx;
            float y0f = floorf(py), x0f = floorf(px);
            float ly = py - y0f, lx = px - x0f;
            int y0 = (int)y0f, x0i = (int)x0f;
            int y1 = y0 + 1,  x1 = x0i + 1;
            float vy0 = (y0  >= 0 && y0  < 64) ? 1.f : 0.f;
            float vy1 = (y1  >= 0 && y1  < 64) ? 1.f : 0.f;
            float vx0 = (x0i >= 0 && x0i < 64) ? 1.f : 0.f;
            float vx1 = (x1  >= 0 && x1  < 64) ? 1.f : 0.f;
            gw[it][0] = (1.f-ly)*(1.f-lx)*vy0*vx0;
            gw[it][1] = (1.f-ly)*lx      *vy0*vx1;
            gw[it][2] = ly      *(1.f-lx)*vy1*vx0;
            gw[it][3] = ly      *lx      *vy1*vx1;
            int y0c = min(max(y0, 0), 63), y1c = min(max(y1, 0), 63);
            int x0c = min(max(x0i,0), 63), x1c = min(max(x1, 0), 63);
            uint32_t rowb = (uint32_t)(bb << 12);
            gb[it][0] = (rowb + (y0c << 6) + x0c) << 9;
            gb[it][1] = (rowb + (y0c << 6) + x1c) << 9;
            gb[it][2] = (rowb + (y1c << 6) + x0c) << 9;
            gb[it][3] = (rowb + (y1c << 6) + x1c) << 9;
        }
    };

    const char* nb = (const char*)g_nhwcH;

    auto gather = [&](int it, int c0, uint4* cd) {
        uint32_t cho = (uint32_t)(c0 * 2) + chb;
        cd[0] = *(const uint4*)(nb + gb[it][0] + cho);
        cd[1] = *(const uint4*)(nb + gb[it][1] + cho);
        cd[2] = *(const uint4*)(nb + gb[it][2] + cho);
        cd[3] = *(const uint4*)(nb + gb[it][3] + cho);
    };

    auto combine_sts = [&](int it, const uint4* cd, uint32_t abuf_off) {
        uint4 pk;
        uint32_t* po = (uint32_t*)&pk;
        #pragma unroll
        for (int j = 0; j < 4; j++) {
            float2 f0 = __half22float2(((const __half2*)&cd[0])[j]);
            float2 f1 = __half22float2(((const __half2*)&cd[1])[j]);
            float2 f2 = __half22float2(((const __half2*)&cd[2])[j]);
            float2 f3 = __half22float2(((const __half2*)&cd[3])[j]);
            float rx = gw[it][0]*f0.x + gw[it][1]*f1.x + gw[it][2]*f2.x + gw[it][3]*f3.x;
            float ry = gw[it][0]*f0.y + gw[it][1]*f1.y + gw[it][2]*f2.y + gw[it][3]*f3.y;
            __half2 h = __floats2half2_rn(rx, ry);
            po[j] = *(uint32_t*)&h;
        }
        *(uint4*)(dsmp + abuf_off + growl[it]*80 + (lid & 3)*16) = pk;
    };

    auto loadB = [&](int c, int p) {
        uint32_t sb = sbase + BBASE + p * BPL;
        size_t kOff = (size_t)c * KC;
        #pragma unroll
        for (int i = 0; i < 4; i++) {
            int idx = tid + i*256;
            int rr = idx >> 2;
            int j  = idx & 3;
            cpa16(sb + rr*80 + j*16, g_B + (size_t)rr*Kd + kOff + j*8);
        }
        asm volatile("cp.async.commit_group;");
    };

    calc_tap(0);
    {
        uint4 cd[4];
        gather(0, 0, cd); combine_sts(0, cd, 0);
        gather(1, 0, cd); combine_sts(1, cd, 0);
    }
    loadB(0, 0);
    loadB(1, 1);
    loadB(2, 2);

    for (int c = 0; c < NCH; c++) {
        if (c + 3 < NCH) {
            asm volatile("cp.async.wait_group 2;" ::: "memory");
        } else if (c + 2 < NCH) {
            asm volatile("cp.async.wait_group 1;" ::: "memory");
        } else {
            asm volatile("cp.async.wait_group 0;" ::: "memory");
        }
        __syncthreads();

        const int prep = (c + 1 < NCH);
        const int cn = c + 1;
        if (prep && ((cn & 7) == 0)) calc_tap(cn >> 3);
        const int c0n = (cn & 7) * 32;
        const uint32_t abuf_n = (uint32_t)((cn & 1) * APL);

        uint32_t sbB = sbase + BBASE + (c & 3) * BPL;
        uint32_t sbA = sbase + (c & 1) * APL;

        uint4 cd0[4], cd1[4];
        if (prep) gather(0, c0n, cd0);

        // kh = 0
        {
            uint32_t ah[4][4];
            #pragma unroll
            for (int mt = 0; mt < 4; mt++)
                LDMX4(ah[mt], sbA + a_off + mt*(16*80));
            #pragma unroll
            for (int tp = 0; tp < 4; tp++) {
                uint32_t bfr[4];
                LDMX4(bfr, sbB + bm_off + tp*(16*80));
                #pragma unroll
                for (int q = 0; q < 2; q++) {
                    int nt = tp*2 + q;
                    #pragma unroll
                    for (int mt = 0; mt < 4; mt++)
                        MMA16816(acc[mt][nt], ah[mt], bfr[2*q], bfr[2*q+1]);
                }
            }
        }
        if (prep) { combine_sts(0, cd0, abuf_n); gather(1, c0n, cd1); }
        // kh = 1
        {
            uint32_t ah[4][4];
            #pragma unroll
            for (int mt = 0; mt < 4; mt++)
                LDMX4(ah[mt], sbA + a_off + mt*(16*80) + 32);
            #pragma unroll
            for (int tp = 0; tp < 4; tp++) {
                uint32_t bfr[4];
                LDMX4(bfr, sbB + bm_off + tp*(16*80) + 32);
                #pragma unroll
                for (int q = 0; q < 2; q++) {
                    int nt = tp*2 + q;
                    #pragma unroll
                    for (int mt = 0; mt < 4; mt++)
                        MMA16816(acc[mt][nt], ah[mt], bfr[2*q], bfr[2*q+1]);
                }
            }
        }
        if (prep) combine_sts(1, cd1, abuf_n);
        if (c + 3 < NCH) loadB(c + 3, (c + 3) & 3);
    }

    #pragma unroll
    for (int mt = 0; mt < 4; mt++) {
        int mA = m0 + warpM*64 + mt*16 + (lid >> 2);
        int mB = mA + 8;
        int bA = mA >> 12, bB = mB >> 12;
        int pA = mA & 4095, pB = mB & 4095;
        #pragma unroll
        for (int nt = 0; nt < 8; nt++) {
            int o = warpN*64 + nt*8 + (lid & 3)*2;
            float bv0 = g_bias2[o], bv1 = g_bias2[o + 1];
            float* d = acc[mt][nt];
            out[((size_t)bA << 20) + ((size_t)o << 12)     + pA] = fmaxf(d[0] + bv0, 0.f);
            out[((size_t)bA << 20) + ((size_t)(o+1) << 12) + pA] = fmaxf(d[1] + bv1, 0.f);
            out[((size_t)bB << 20) + ((size_t)o << 12)     + pB] = fmaxf(d[2] + bv0, 0.f);
            out[((size_t)bB << 20) + ((size_t)(o+1) << 12) + pB] = fmaxf(d[3] + bv1, 0.f);
        }
    }
}

// ---------------- launch ----------------
extern "C" void kernel_launch(void* const* d_in, const int* in_sizes, int n_in,
                              void* d_out, int out_size) {
    const float* input  = (const float*)d_in[0];
    const float* w_off  = (const float*)d_in[1];
    const float* b_off  = (const float*)d_in[2];
    const float* weight = (const float*)d_in[3];
    const float* bias   = (const float*)d_in[4];
    const float* gamma  = (const float*)d_in[5];
    const float* beta   = (const float*)d_in[6];
    const float* mean   = (const float*)d_in[7];
    const float* var    = (const float*)d_in[8];
    float* out = (float*)d_out;

    cudaFuncSetAttribute(k_gemm_fused, cudaFuncAttributeMaxDynamicSharedMemorySize, SMEMSZ);
    cudaFuncSetAttribute(k_offset_gemm, cudaFuncAttributeMaxDynamicSharedMemorySize, NSTG2*STG2);

    k_transpose_prep<<<dim3(2, 6, 256), dim3(32, 8)>>>(input, weight, w_off, bias, gamma, beta, mean, var);
    k_offset_gemm<<<Md/128, 256, NSTG2*STG2>>>(b_off);
    k_gemm_fused<<<Md/128, 256, SMEMSZ>>>(out);
}

// round 15
// speedup vs baseline: 1.0927x; 1.0093x over previous
#include <cuda_runtime.h>
#include <cuda_fp16.h>
#include <cstdint>

#define Bsz 4
#define Cch 256
#define Hh  64
#define Ww  64
#define Oo  256
#define Kt  9
#define Md  (Bsz*Hh*Ww)   // 16384
#define Kd  (Cch*Kt)      // 2304

// ---------------- scratch ----------------
__device__ __half g_nhwcH[(size_t)Bsz*Hh*Ww*Cch];   // fp16 NHWC
__device__ __half g_B[(size_t)Oo*Kd];
__device__ __half g_Boff[(size_t)32*Kd];
__device__ float g_bias2[Oo];

// ---------------- helpers ----------------
__device__ __forceinline__ uint32_t smem_u32(const void* p) {
    uint32_t a;
    asm("{ .reg .u64 t; cvta.to.shared.u64 t, %1; cvt.u32.u64 %0, t; }" : "=r"(a) : "l"(p));
    return a;
}
__device__ __forceinline__ void cpa16(uint32_t s, const void* g) {
    asm volatile("cp.async.cg.shared.global [%0], [%1], 16;" :: "r"(s), "l"(g));
}
__device__ __forceinline__ void cpa16z(uint32_t s, const void* g, int valid) {
    asm volatile("cp.async.cg.shared.global [%0], [%1], 16, %2;"
                 :: "r"(s), "l"(g), "r"(valid ? 16 : 0));
}
#define LDMX4(r, addr) \
    asm volatile("ldmatrix.sync.aligned.m8n8.x4.shared.b16 {%0,%1,%2,%3}, [%4];" \
        : "=r"((r)[0]), "=r"((r)[1]), "=r"((r)[2]), "=r"((r)[3]) : "r"(addr))
#define MMA16816(d, a, b0, b1) \
    asm volatile("mma.sync.aligned.m16n8k16.row.col.f32.f16.f16.f32 " \
        "{%0,%1,%2,%3}, {%4,%5,%6,%7}, {%8,%9}, {%0,%1,%2,%3};" \
        : "+f"((d)[0]), "+f"((d)[1]), "+f"((d)[2]), "+f"((d)[3]) \
        : "r"((a)[0]), "r"((a)[1]), "r"((a)[2]), "r"((a)[3]), "r"(b0), "r"(b1))

// ---------------- 1) transpose to fp16 NHWC + weight prep ----------------
__global__ void k_transpose_prep(const float* __restrict__ in,
                                 const float* __restrict__ w,
                                 const float* __restrict__ w_off,
                                 const float* __restrict__ bias,
                                 const float* __restrict__ gamma,
                                 const float* __restrict__ beta,
                                 const float* __restrict__ mean,
                                 const float* __restrict__ var) {
    const int tx = threadIdx.x, ty = threadIdx.y;
    if (blockIdx.y == 4) {
        int o = blockIdx.z;
        int tid = ty * 32 + tx;
        float inv = gamma[o] * rsqrtf(var[o] + 1e-5f);
        int kd0 = blockIdx.x * (Kd/2);
        for (int i = tid; i < Kd/2; i += 256) {
            int kd = kd0 + i;
            int tap = kd >> 8, c = kd & 255;
            g_B[(size_t)o*Kd + kd] = __float2half_rn(w[((size_t)(o*Cch + c))*9 + tap] * inv);
        }
        if (tid == 0 && blockIdx.x == 0)
            g_bias2[o] = bias[o]*inv + beta[o] - mean[o]*inv;
        return;
    }
    if (blockIdx.y == 5) {
        int j = blockIdx.z;
        if (j >= 32 || blockIdx.x != 0) return;
        int tid = ty * 32 + tx;
        for (int kd = tid; kd < Kd; kd += 256) {
            int tap = kd >> 8, c = kd & 255;
            __half v = __float2half_rn(0.f);
            if (j < 18) v = __float2half_rn(w_off[((size_t)(j*Cch + c))*9 + tap]);
            g_Boff[(size_t)j*Kd + kd] = v;
        }
        return;
    }
    __shared__ float t[64][33];
    const int x0 = blockIdx.x * 32;
    const int c0 = blockIdx.y * 64;
    const int bh = blockIdx.z;
    const int b = bh >> 6, y = bh & 63;
    const float* ib = in + (((size_t)(b*Cch + c0))*Hh + y)*Ww + x0;
    #pragma unroll
    for (int i = 0; i < 8; i++) {
        int r = ty + i*8;
        t[r][tx] = ib[(size_t)r*Hh*Ww + tx];
    }
    __syncthreads();
    __half* ob = g_nhwcH + (((size_t)(b*Hh + y)*Ww + x0) << 8) + c0;
    #pragma unroll
    for (int i = 0; i < 4; i++) {
        int x = ty + i*8;
        __half2 h = __floats2half2_rn(t[2*tx][x], t[2*tx + 1][x]);
        *(__half2*)(ob + ((size_t)x << 8) + 2*tx) = h;
    }
}

// ---------------- 2) merged: offset GEMM prologue + fused sample GEMM ----------------
// phase-1 (offset conv): KC2=32 chunks, 4-stage pipe in the low 51200 bytes of smem
#define KC2 32
#define NCH2 (Kd/KC2)        // 72
#define APL2 10240
#define BSM2 2560
#define STG2 (APL2 + BSM2)   // 12800
// phase-2 (main GEMM): R12 config
#define KC 32
#define NCH (Kd/KC)          // 72
#define APL 10240
#define BPL 20480
#define BBASE (2*APL)
#define GEMMSZ (2*APL + 4*BPL)      // 102400
#define SOFF GEMMSZ                 // offsets: 18 x 128 floats
#define SMEMSZ (GEMMSZ + 18*128*4)  // 111616

__global__ __launch_bounds__(256, 1) void k_fused_all(float* __restrict__ out,
                                                      const float* __restrict__ b_off) {
    extern __shared__ char dsm[];
    const uint32_t sbase = smem_u32(dsm);
    char* dsmp = dsm;
    float* s_off = (float*)(dsm + SOFF);
    const int tid = threadIdx.x, lid = tid & 31, wid = tid >> 5;
    const int m0 = blockIdx.x * 128;
    const int bb = m0 >> 12;
    const int y0 = (m0 >> 6) & 63;
    const int pbase = m0 & 4095;

    // ================= phase 1: offset conv for own 128 pixels =================
    {
        float acc[4][4];
        #pragma unroll
        for (int nt = 0; nt < 4; nt++)
            #pragma unroll
            for (int j = 0; j < 4; j++) acc[nt][j] = 0.f;

        const uint32_t a_off = (uint32_t)((wid*16 + (lid & 15)) * 80 + (lid >> 4) * 16);
        const uint32_t b_offs = (uint32_t)(((lid & 7) + ((lid >> 4) & 1)*8) * 80
                                           + ((lid >> 3) & 1) * 16);

        auto load = [&](int c, int p) {
            uint32_t sb = sbase + p * STG2;
            int tap = c >> 3;
            int ky = tap / 3 - 1, kx = tap % 3 - 1;
            int c0 = (c & 7) * 32;
            #pragma unroll
            for (int i = 0; i < 2; i++) {
                int idx = tid + i*256;
                int r   = idx >> 2;
                int j   = idx & 3;
                int ry = y0 + (r >> 6) + ky;
                int rx = (r & 63) + kx;
                int valid = ((unsigned)ry < 64u) && ((unsigned)rx < 64u);
                int ryc = min(max(ry, 0), 63), rxc = min(max(rx, 0), 63);
                const __half* src = g_nhwcH + (((size_t)(bb*Hh + ryc)*Ww + rxc) << 8) + c0 + j*8;
                cpa16z(sb + r*80 + j*16, src, valid);
            }
            if (tid < 128) {
                int rr = tid >> 2;
                int j  = tid & 3;
                cpa16(sb + APL2 + rr*80 + j*16, g_Boff + (size_t)rr*Kd + tap*Cch + c0 + j*8);
            }
            asm volatile("cp.async.commit_group;");
        };

        load(0, 0);
        load(1, 1);
        load(2, 2);

        for (int c = 0; c < NCH2; c++) {
            int p = c & 3;
            if (c + 3 < NCH2) {
                load(c + 3, (c + 3) & 3);
                asm volatile("cp.async.wait_group 3;" ::: "memory");
            } else if (c + 2 < NCH2) {
                asm volatile("cp.async.wait_group 2;" ::: "memory");
            } else if (c + 1 < NCH2) {
                asm volatile("cp.async.wait_group 1;" ::: "memory");
            } else {
                asm volatile("cp.async.wait_group 0;" ::: "memory");
            }
            __syncthreads();

            uint32_t sb = sbase + p * STG2;
            #pragma unroll
            for (int kh = 0; kh < 2; kh++) {
                uint32_t ah[4];
                LDMX4(ah, sb + a_off + kh*32);
                #pragma unroll
                for (int tp = 0; tp < 2; tp++) {
                    uint32_t bbq[4];
                    LDMX4(bbq, sb + APL2 + b_offs + tp*(16*80) + kh*32);
                    #pragma unroll
                    for (int q = 0; q < 2; q++)
                        MMA16816(acc[tp*2 + q], ah, bbq[2*q], bbq[2*q+1]);
                }
            }
            __syncthreads();
        }

        // epilogue -> smem offsets
        int mA = wid*16 + (lid >> 2);
        int mB = mA + 8;
        #pragma unroll
        for (int nt = 0; nt < 4; nt++) {
            int j0 = nt*8 + (lid & 3)*2;
            float* d = acc[nt];
            if (j0 < 18) {
                float bv = b_off[j0];
                s_off[j0*128 + mA] = d[0] + bv;
                s_off[j0*128 + mB] = d[2] + bv;
            }
            if (j0 + 1 < 18) {
                float bv = b_off[j0 + 1];
                s_off[(j0 + 1)*128 + mA] = d[1] + bv;
                s_off[(j0 + 1)*128 + mB] = d[3] + bv;
            }
        }
    }
    __syncthreads();

    // ================= phase 2: fused sample + main GEMM =================
    const int warpM = wid & 1, warpN = wid >> 1;   // 2 x 4, warp tile 64x64

    float acc[4][8][4];
    #pragma unroll
    for (int mt = 0; mt < 4; mt++)
        #pragma unroll
        for (int nt = 0; nt < 8; nt++)
            #pragma unroll
            for (int j = 0; j < 4; j++) acc[mt][nt][j] = 0.f;

    const uint32_t a_off = (uint32_t)((warpM*64 + (lid & 15)) * 80 + (lid >> 4) * 16);
    const uint32_t bm_off = (uint32_t)((warpN*64 + (lid & 7) + ((lid >> 4) & 1)*8) * 80
                                       + ((lid >> 3) & 1) * 16);

    float gw[2][4];
    uint32_t gb[2][4];
    const int growl[2] = { wid*16 + (lid >> 2), wid*16 + 8 + (lid >> 2) };
    const uint32_t chb = (uint32_t)((lid & 3) * 16);

    auto calc_tap = [&](int tap) {
        #pragma unroll
        for (int it = 0; it < 2; it++) {
            int pr = growl[it];
            int p = pbase + pr;
            int y = (p >> 6) & 63, x = p & 63;
            float dy = s_off[(2*tap)*128 + pr];
            float dx = s_off[(2*tap + 1)*128 + pr];
            float py = (float)(y - 1 + tap/3) + dy;
            float px = (float)(x - 1 + tap%3) + dx;
            float y0f = floorf(py), x0f = floorf(px);
            float ly = py - y0f, lx = px - x0f;
            int yy0 = (int)y0f, x0i = (int)x0f;
            int yy1 = yy0 + 1,  x1 = x0i + 1;
            float vy0 = (yy0 >= 0 && yy0 < 64) ? 1.f : 0.f;
            float vy1 = (yy1 >= 0 && yy1 < 64) ? 1.f : 0.f;
            float vx0 = (x0i >= 0 && x0i < 64) ? 1.f : 0.f;
            float vx1 = (x1  >= 0 && x1  < 64) ? 1.f : 0.f;
            gw[it][0] = (1.f-ly)*(1.f-lx)*vy0*vx0;
            gw[it][1] = (1.f-ly)*lx      *vy0*vx1;
            gw[it][2] = ly      *(1.f-lx)*vy1*vx0;
            gw[it][3] = ly      *lx      *vy1*vx1;
            int y0c = min(max(yy0, 0), 63), y1c = min(max(yy1, 0), 63);
            int x0c = min(max(x0i, 0), 63), x1c = min(max(x1,  0), 63);
            uint32_t rowb = (uint32_t)(bb << 12);
            gb[it][0] = (rowb + (y0c << 6) + x0c) << 9;
            gb[it][1] = (rowb + (y0c << 6) + x1c) << 9;
            gb[it][2] = (rowb + (y1c << 6) + x0c) << 9;
            gb[it][3] = (rowb + (y1c << 6) + x1c) << 9;
        }
    };

    const char* nb = (const char*)g_nhwcH;

    auto gather = [&](int it, int c0, uint4* cd) {
        uint32_t cho = (uint32_t)(c0 * 2) + chb;
        cd[0] = *(const uint4*)(nb + gb[it][0] + cho);
        cd[1] = *(const uint4*)(nb + gb[it][1] + cho);
        cd[2] = *(const uint4*)(nb + gb[it][2] + cho);
        cd[3] = *(const uint4*)(nb + gb[it][3] + cho);
    };

    auto combine_sts = [&](int it, const uint4* cd, uint32_t abuf_off) {
        uint4 pk;
        uint32_t* po = (uint32_t*)&pk;
        #pragma unroll
        for (int j = 0; j < 4; j++) {
            float2 f0 = __half22float2(((const __half2*)&cd[0])[j]);
            float2 f1 = __half22float2(((const __half2*)&cd[1])[j]);
            float2 f2 = __half22float2(((const __half2*)&cd[2])[j]);
            float2 f3 = __half22float2(((const __half2*)&cd[3])[j]);
            float rx = gw[it][0]*f0.x + gw[it][1]*f1.x + gw[it][2]*f2.x + gw[it][3]*f3.x;
            float ry = gw[it][0]*f0.y + gw[it][1]*f1.y + gw[it][2]*f2.y + gw[it][3]*f3.y;
            __half2 h = __floats2half2_rn(rx, ry);
            po[j] = *(uint32_t*)&h;
        }
        *(uint4*)(dsmp + abuf_off + growl[it]*80 + (lid & 3)*16) = pk;
    };

    auto loadB = [&](int c, int p) {
        uint32_t sb = sbase + BBASE + p * BPL;
        size_t kOff = (size_t)c * KC;
        #pragma unroll
        for (int i = 0; i < 4; i++) {
            int idx = tid + i*256;
            int rr = idx >> 2;
            int j  = idx & 3;
            cpa16(sb + rr*80 + j*16, g_B + (size_t)rr*Kd + kOff + j*8);
        }
        asm volatile("cp.async.commit_group;");
    };

    calc_tap(0);
    {
        uint4 cd[4];
        gather(0, 0, cd); combine_sts(0, cd, 0);
        gather(1, 0, cd); combine_sts(1, cd, 0);
    }
    loadB(0, 0);
    loadB(1, 1);
    loadB(2, 2);

    for (int c = 0; c < NCH; c++) {
        if (c + 3 < NCH) {
            asm volatile("cp.async.wait_group 2;" ::: "memory");
        } else if (c + 2 < NCH) {
            asm volatile("cp.async.wait_group 1;" ::: "memory");
        } else {
            asm volatile("cp.async.wait_group 0;" ::: "memory");
        }
        __syncthreads();

        const int prep = (c + 1 < NCH);
        const int cn = c + 1;
        if (prep && ((cn & 7) == 0)) calc_tap(cn >> 3);
        const int c0n = (cn & 7) * 32;
        const uint32_t abuf_n = (uint32_t)((cn & 1) * APL);

        uint32_t sbB = sbase + BBASE + (c & 3) * BPL;
        uint32_t sbA = sbase + (c & 1) * APL;

        uint4 cd0[4], cd1[4];
        if (prep) gather(0, c0n, cd0);

        // kh = 0
        {
            uint32_t ah[4][4];
            #pragma unroll
            for (int mt = 0; mt < 4; mt++)
                LDMX4(ah[mt], sbA + a_off + mt*(16*80));
            #pragma unroll
            for (int tp = 0; tp < 4; tp++) {
                uint32_t bfr[4];
                LDMX4(bfr, sbB + bm_off + tp*(16*80));
                #pragma unroll
                for (int q = 0; q < 2; q++) {
                    int nt = tp*2 + q;
                    #pragma unroll
                    for (int mt = 0; mt < 4; mt++)
                        MMA16816(acc[mt][nt], ah[mt], bfr[2*q], bfr[2*q+1]);
                }
            }
        }
        if (prep) { combine_sts(0, cd0, abuf_n); gather(1, c0n, cd1); }
        // kh = 1
        {
            uint32_t ah[4][4];
            #pragma unroll
            for (int mt = 0; mt < 4; mt++)
                LDMX4(ah[mt], sbA + a_off + mt*(16*80) + 32);
            #pragma unroll
            for (int tp = 0; tp < 4; tp++) {
                uint32_t bfr[4];
                LDMX4(bfr, sbB + bm_off + tp*(16*80) + 32);
                #pragma unroll
                for (int q = 0; q < 2; q++) {
                    int nt = tp*2 + q;
                    #pragma unroll
                    for (int mt = 0; mt < 4; mt++)
                        MMA16816(acc[mt][nt], ah[mt], bfr[2*q], bfr[2*q+1]);
                }
            }
        }
        if (prep) combine_sts(1, cd1, abuf_n);
        if (c + 3 < NCH) loadB(c + 3, (c + 3) & 3);
    }

    // epilogue: bias + relu, NCHW stores
    #pragma unroll
    for (int mt = 0; mt < 4; mt++) {
        int mA = m0 + warpM*64 + mt*16 + (lid >> 2);
        int mB = mA + 8;
        int bA = mA >> 12, bB = mB >> 12;
        int pA = mA & 4095, pB = mB & 4095;
        #pragma unroll
        for (int nt = 0; nt < 8; nt++) {
            int o = warpN*64 + nt*8 + (lid & 3)*2;
            float bv0 = g_bias2[o], bv1 = g_bias2[o + 1];
            float* d = acc[mt][nt];
            out[((size_t)bA << 20) + ((size_t)o << 12)     + pA] = fmaxf(d[0] + bv0, 0.f);
            out[((size_t)bA << 20) + ((size_t)(o+1) << 12) + pA] = fmaxf(d[1] + bv1, 0.f);
            out[((size_t)bB << 20) + ((size_t)o << 12)     + pB] = fmaxf(d[2] + bv0, 0.f);
            out[((size_t)bB << 20) + ((size_t)(o+1) << 12) + pB] = fmaxf(d[3] + bv1, 0.f);
        }
    }
}

// ---------------- launch ----------------
extern "C" void kernel_launch(void* const* d_in, const int* in_sizes, int n_in,
                              void* d_out, int out_size) {
    const float* input  = (const float*)d_in[0];
    const float* w_off  = (const float*)d_in[1];
    const float* b_off  = (const float*)d_in[2];
    const float* weight = (const float*)d_in[3];
    const float* bias   = (const float*)d_in[4];
    const float* gamma  = (const float*)d_in[5];
    const float* beta   = (const float*)d_in[6];
    const float* mean   = (const float*)d_in[7];
    const float* var    = (const float*)d_in[8];
    float* out = (float*)d_out;

    cudaFuncSetAttribute(k_fused_all, cudaFuncAttributeMaxDynamicSharedMemorySize, SMEMSZ);

    k_transpose_prep<<<dim3(2, 6, 256), dim3(32, 8)>>>(input, weight, w_off, bias, gamma, beta, mean, var);
    k_fused_all<<<Md/128, 256, SMEMSZ>>>(out, b_off);
}

// round 16
// speedup vs baseline: 1.1986x; 1.0969x over previous
#include <cuda_runtime.h>
#include <cuda_fp16.h>
#include <cstdint>

#define Bsz 4
#define Cch 256
#define Hh  64
#define Ww  64
#define Oo  256
#define Kt  9
#define Md  (Bsz*Hh*Ww)   // 16384
#define Kd  (Cch*Kt)      // 2304

// ---------------- scratch ----------------
__device__ __half g_nhwcH[(size_t)Bsz*Hh*Ww*Cch];   // fp16 NHWC
__device__ __half g_B[(size_t)Oo*Kd];
__device__ __half g_Boff[(size_t)32*Kd];
__device__ float g_bias2[Oo];

// ---------------- helpers ----------------
__device__ __forceinline__ uint32_t smem_u32(const void* p) {
    uint32_t a;
    asm("{ .reg .u64 t; cvta.to.shared.u64 t, %1; cvt.u32.u64 %0, t; }" : "=r"(a) : "l"(p));
    return a;
}
__device__ __forceinline__ void cpa16(uint32_t s, const void* g) {
    asm volatile("cp.async.cg.shared.global [%0], [%1], 16;" :: "r"(s), "l"(g));
}
__device__ __forceinline__ void cpa16z(uint32_t s, const void* g, int valid) {
    asm volatile("cp.async.cg.shared.global [%0], [%1], 16, %2;"
                 :: "r"(s), "l"(g), "r"(valid ? 16 : 0));
}
#define LDMX4(r, addr) \
    asm volatile("ldmatrix.sync.aligned.m8n8.x4.shared.b16 {%0,%1,%2,%3}, [%4];" \
        : "=r"((r)[0]), "=r"((r)[1]), "=r"((r)[2]), "=r"((r)[3]) : "r"(addr))
#define MMA16816(d, a, b0, b1) \
    asm volatile("mma.sync.aligned.m16n8k16.row.col.f32.f16.f16.f32 " \
        "{%0,%1,%2,%3}, {%4,%5,%6,%7}, {%8,%9}, {%0,%1,%2,%3};" \
        : "+f"((d)[0]), "+f"((d)[1]), "+f"((d)[2]), "+f"((d)[3]) \
        : "r"((a)[0]), "r"((a)[1]), "r"((a)[2]), "r"((a)[3]), "r"(b0), "r"(b1))

// ---------------- 1) transpose to fp16 NHWC + weight prep ----------------
__global__ void k_transpose_prep(const float* __restrict__ in,
                                 const float* __restrict__ w,
                                 const float* __restrict__ w_off,
                                 const float* __restrict__ bias,
                                 const float* __restrict__ gamma,
                                 const float* __restrict__ beta,
                                 const float* __restrict__ mean,
                                 const float* __restrict__ var) {
    const int tx = threadIdx.x, ty = threadIdx.y;
    if (blockIdx.y == 4) {
        int o = blockIdx.z;
        int tid = ty * 32 + tx;
        float inv = gamma[o] * rsqrtf(var[o] + 1e-5f);
        int kd0 = blockIdx.x * (Kd/2);
        for (int i = tid; i < Kd/2; i += 256) {
            int kd = kd0 + i;
            int tap = kd >> 8, c = kd & 255;
            g_B[(size_t)o*Kd + kd] = __float2half_rn(w[((size_t)(o*Cch + c))*9 + tap] * inv);
        }
        if (tid == 0 && blockIdx.x == 0)
            g_bias2[o] = bias[o]*inv + beta[o] - mean[o]*inv;
        return;
    }
    if (blockIdx.y == 5) {
        int j = blockIdx.z;
        if (j >= 32 || blockIdx.x != 0) return;
        int tid = ty * 32 + tx;
        for (int kd = tid; kd < Kd; kd += 256) {
            int tap = kd >> 8, c = kd & 255;
            __half v = __float2half_rn(0.f);
            if (j < 18) v = __float2half_rn(w_off[((size_t)(j*Cch + c))*9 + tap]);
            g_Boff[(size_t)j*Kd + kd] = v;
        }
        return;
    }
    __shared__ float t[64][33];
    const int x0 = blockIdx.x * 32;
    const int c0 = blockIdx.y * 64;
    const int bh = blockIdx.z;
    const int b = bh >> 6, y = bh & 63;
    const float* ib = in + (((size_t)(b*Cch + c0))*Hh + y)*Ww + x0;
    #pragma unroll
    for (int i = 0; i < 8; i++) {
        int r = ty + i*8;
        t[r][tx] = ib[(size_t)r*Hh*Ww + tx];
    }
    __syncthreads();
    __half* ob = g_nhwcH + (((size_t)(b*Hh + y)*Ww + x0) << 8) + c0;
    #pragma unroll
    for (int i = 0; i < 4; i++) {
        int x = ty + i*8;
        __half2 h = __floats2half2_rn(t[2*tx][x], t[2*tx + 1][x]);
        *(__half2*)(ob + ((size_t)x << 8) + 2*tx) = h;
    }
}

// ---------------- 2) merged: offset GEMM prologue + fused sample GEMM ----------------
// phase-2 (main GEMM) region
#define KC 32
#define NCH (Kd/KC)          // 72
#define APL 10240
#define BPL 20480
#define BBASE (2*APL)
#define GEMMSZ (2*APL + 4*BPL)      // 102400
#define SOFF GEMMSZ                 // offsets: 18 x 128 floats
// phase-1 staging region (disjoint, so B prefetch can proceed during phase-1)
#define KC2 32
#define NCH2 (Kd/KC2)        // 72
#define APL2 10240
#define BSM2 2560
#define STG2 (APL2 + BSM2)   // 12800
#define P1BASE (SOFF + 18*128*4)    // 111616
#define SMEMSZ (P1BASE + 4*STG2)    // 162816

__global__ __launch_bounds__(256, 1) void k_fused_all(float* __restrict__ out,
                                                      const float* __restrict__ b_off) {
    extern __shared__ char dsm[];
    const uint32_t sbase = smem_u32(dsm);
    char* dsmp = dsm;
    float* s_off = (float*)(dsm + SOFF);
    const int tid = threadIdx.x, lid = tid & 31, wid = tid >> 5;
    const int m0 = blockIdx.x * 128;
    const int bb = m0 >> 12;
    const int y0 = (m0 >> 6) & 63;
    const int pbase = m0 & 4095;

    // B loader for phase-2 (used for prefetch during phase-1 too)
    auto loadB = [&](int c, int p) {
        uint32_t sb = sbase + BBASE + p * BPL;
        size_t kOff = (size_t)c * KC;
        #pragma unroll
        for (int i = 0; i < 4; i++) {
            int idx = tid + i*256;
            int rr = idx >> 2;
            int j  = idx & 3;
            cpa16(sb + rr*80 + j*16, g_B + (size_t)rr*Kd + kOff + j*8);
        }
        asm volatile("cp.async.commit_group;");
    };

    // prefetch phase-2's first 3 B stages; completes during phase-1
    loadB(0, 0);
    loadB(1, 1);
    loadB(2, 2);

    // ================= phase 1: offset conv for own 128 pixels =================
    {
        float acc[4][4];
        #pragma unroll
        for (int nt = 0; nt < 4; nt++)
            #pragma unroll
            for (int j = 0; j < 4; j++) acc[nt][j] = 0.f;

        const uint32_t a_off = (uint32_t)(P1BASE + (wid*16 + (lid & 15)) * 80 + (lid >> 4) * 16);
        const uint32_t b_offs = (uint32_t)(P1BASE + APL2 + ((lid & 7) + ((lid >> 4) & 1)*8) * 80
                                           + ((lid >> 3) & 1) * 16);

        auto load = [&](int c, int p) {
            uint32_t sb = sbase + P1BASE + p * STG2;
            int tap = c >> 3;
            int ky = tap / 3 - 1, kx = tap % 3 - 1;
            int c0 = (c & 7) * 32;
            #pragma unroll
            for (int i = 0; i < 2; i++) {
                int idx = tid + i*256;
                int r   = idx >> 2;
                int j   = idx & 3;
                int ry = y0 + (r >> 6) + ky;
                int rx = (r & 63) + kx;
                int valid = ((unsigned)ry < 64u) && ((unsigned)rx < 64u);
                int ryc = min(max(ry, 0), 63), rxc = min(max(rx, 0), 63);
                const __half* src = g_nhwcH + (((size_t)(bb*Hh + ryc)*Ww + rxc) << 8) + c0 + j*8;
                cpa16z(sb + r*80 + j*16, src, valid);
            }
            if (tid < 128) {
                int rr = tid >> 2;
                int j  = tid & 3;
                cpa16(sb + APL2 + rr*80 + j*16, g_Boff + (size_t)rr*Kd + tap*Cch + c0 + j*8);
            }
            asm volatile("cp.async.commit_group;");
        };

        load(0, 0);
        load(1, 1);
        load(2, 2);

        for (int c = 0; c < NCH2; c++) {
            int p = c & 3;
            if (c + 3 < NCH2) {
                load(c + 3, (c + 3) & 3);
                asm volatile("cp.async.wait_group 3;" ::: "memory");
            } else if (c + 2 < NCH2) {
                asm volatile("cp.async.wait_group 2;" ::: "memory");
            } else if (c + 1 < NCH2) {
                asm volatile("cp.async.wait_group 1;" ::: "memory");
            } else {
                asm volatile("cp.async.wait_group 0;" ::: "memory");
            }
            __syncthreads();

            uint32_t sb = sbase + P1BASE - P1BASE;   // base handled in offsets below
            (void)sb;
            uint32_t stg = (uint32_t)(p * STG2);
            #pragma unroll
            for (int kh = 0; kh < 2; kh++) {
                uint32_t ah[4];
                LDMX4(ah, sbase + a_off - 0 + stg + kh*32);
                #pragma unroll
                for (int tp = 0; tp < 2; tp++) {
                    uint32_t bbq[4];
                    LDMX4(bbq, sbase + b_offs + stg + tp*(16*80) + kh*32);
                    #pragma unroll
                    for (int q = 0; q < 2; q++)
                        MMA16816(acc[tp*2 + q], ah, bbq[2*q], bbq[2*q+1]);
                }
            }
            __syncthreads();
        }

        // epilogue -> smem offsets
        int mA = wid*16 + (lid >> 2);
        int mB = mA + 8;
        #pragma unroll
        for (int nt = 0; nt < 4; nt++) {
            int j0 = nt*8 + (lid & 3)*2;
            float* d = acc[nt];
            if (j0 < 18) {
                float bv = b_off[j0];
                s_off[j0*128 + mA] = d[0] + bv;
                s_off[j0*128 + mB] = d[2] + bv;
            }
            if (j0 + 1 < 18) {
                float bv = b_off[j0 + 1];
                s_off[(j0 + 1)*128 + mA] = d[1] + bv;
                s_off[(j0 + 1)*128 + mB] = d[3] + bv;
            }
        }
    }
    __syncthreads();

    // ================= phase 2: fused sample + main GEMM =================
    const int warpM = wid & 1, warpN = wid >> 1;   // 2 x 4, warp tile 64x64

    float acc[4][8][4];
    #pragma unroll
    for (int mt = 0; mt < 4; mt++)
        #pragma unroll
        for (int nt = 0; nt < 8; nt++)
            #pragma unroll
            for (int j = 0; j < 4; j++) acc[mt][nt][j] = 0.f;

    const uint32_t a_off = (uint32_t)((warpM*64 + (lid & 15)) * 80 + (lid >> 4) * 16);
    const uint32_t bm_off = (uint32_t)((warpN*64 + (lid & 7) + ((lid >> 4) & 1)*8) * 80
                                       + ((lid >> 3) & 1) * 16);

    __half2 gh[2][4];
    uint32_t gb[2][4];
    const int growl[2] = { wid*16 + (lid >> 2), wid*16 + 8 + (lid >> 2) };
    const uint32_t chb = (uint32_t)((lid & 3) * 16);

    auto calc_tap = [&](int tap) {
        #pragma unroll
        for (int it = 0; it < 2; it++) {
            int pr = growl[it];
            int p = pbase + pr;
            int y = (p >> 6) & 63, x = p & 63;
            float dy = s_off[(2*tap)*128 + pr];
            float dx = s_off[(2*tap + 1)*128 + pr];
            float py = (float)(y - 1 + tap/3) + dy;
            float px = (float)(x - 1 + tap%3) + dx;
            float y0f = floorf(py), x0f = floorf(px);
            float ly = py - y0f, lx = px - x0f;
            int yy0 = (int)y0f, x0i = (int)x0f;
            int yy1 = yy0 + 1,  x1 = x0i + 1;
            float vy0 = (yy0 >= 0 && yy0 < 64) ? 1.f : 0.f;
            float vy1 = (yy1 >= 0 && yy1 < 64) ? 1.f : 0.f;
            float vx0 = (x0i >= 0 && x0i < 64) ? 1.f : 0.f;
            float vx1 = (x1  >= 0 && x1  < 64) ? 1.f : 0.f;
            gh[it][0] = __float2half2_rn((1.f-ly)*(1.f-lx)*vy0*vx0);
            gh[it][1] = __float2half2_rn((1.f-ly)*lx      *vy0*vx1);
            gh[it][2] = __float2half2_rn(ly      *(1.f-lx)*vy1*vx0);
            gh[it][3] = __float2half2_rn(ly      *lx      *vy1*vx1);
            int y0c = min(max(yy0, 0), 63), y1c = min(max(yy1, 0), 63);
            int x0c = min(max(x0i, 0), 63), x1c = min(max(x1,  0), 63);
            uint32_t rowb = (uint32_t)(bb << 12);
            gb[it][0] = (rowb + (y0c << 6) + x0c) << 9;
            gb[it][1] = (rowb + (y0c << 6) + x1c) << 9;
            gb[it][2] = (rowb + (y1c << 6) + x0c) << 9;
            gb[it][3] = (rowb + (y1c << 6) + x1c) << 9;
        }
    };

    const char* nb = (const char*)g_nhwcH;

    auto gather = [&](int it, int c0, uint4* cd) {
        uint32_t cho = (uint32_t)(c0 * 2) + chb;
        cd[0] = *(const uint4*)(nb + gb[it][0] + cho);
        cd[1] = *(const uint4*)(nb + gb[it][1] + cho);
        cd[2] = *(const uint4*)(nb + gb[it][2] + cho);
        cd[3] = *(const uint4*)(nb + gb[it][3] + cho);
    };

    auto combine_sts = [&](int it, const uint4* cd, uint32_t abuf_off) {
        uint4 pk;
        __half2* po = (__half2*)&pk;
        const __half2* f0 = (const __half2*)&cd[0];
        const __half2* f1 = (const __half2*)&cd[1];
        const __half2* f2 = (const __half2*)&cd[2];
        const __half2* f3 = (const __half2*)&cd[3];
        #pragma unroll
        for (int j = 0; j < 4; j++) {
            __half2 r = __hmul2(gh[it][0], f0[j]);
            r = __hfma2(gh[it][1], f1[j], r);
            r = __hfma2(gh[it][2], f2[j], r);
            r = __hfma2(gh[it][3], f3[j], r);
            po[j] = r;
        }
        *(uint4*)(dsmp + abuf_off + growl[it]*80 + (lid & 3)*16) = pk;
    };

    // prologue: A(0); B(0..2) already prefetched before phase 1
    calc_tap(0);
    {
        uint4 cd[4];
        gather(0, 0, cd); combine_sts(0, cd, 0);
        gather(1, 0, cd); combine_sts(1, cd, 0);
    }

    for (int c = 0; c < NCH; c++) {
        if (c + 3 < NCH) {
            asm volatile("cp.async.wait_group 2;" ::: "memory");
        } else if (c + 2 < NCH) {
            asm volatile("cp.async.wait_group 1;" ::: "memory");
        } else {
            asm volatile("cp.async.wait_group 0;" ::: "memory");
        }
        __syncthreads();

        const int prep = (c + 1 < NCH);
        const int cn = c + 1;
        if (prep && ((cn & 7) == 0)) calc_tap(cn >> 3);
        const int c0n = (cn & 7) * 32;
        const uint32_t abuf_n = (uint32_t)((cn & 1) * APL);

        uint32_t sbB = sbase + BBASE + (c & 3) * BPL;
        uint32_t sbA = sbase + (c & 1) * APL;

        uint4 cd0[4], cd1[4];
        if (prep) gather(0, c0n, cd0);

        // kh = 0
        {
            uint32_t ah[4][4];
            #pragma unroll
            for (int mt = 0; mt < 4; mt++)
                LDMX4(ah[mt], sbA + a_off + mt*(16*80));
            #pragma unroll
            for (int tp = 0; tp < 4; tp++) {
                uint32_t bfr[4];
                LDMX4(bfr, sbB + bm_off + tp*(16*80));
                #pragma unroll
                for (int q = 0; q < 2; q++) {
                    int nt = tp*2 + q;
                    #pragma unroll
                    for (int mt = 0; mt < 4; mt++)
                        MMA16816(acc[mt][nt], ah[mt], bfr[2*q], bfr[2*q+1]);
                }
            }
        }
        if (prep) { combine_sts(0, cd0, abuf_n); gather(1, c0n, cd1); }
        // kh = 1
        {
            uint32_t ah[4][4];
            #pragma unroll
            for (int mt = 0; mt < 4; mt++)
                LDMX4(ah[mt], sbA + a_off + mt*(16*80) + 32);
            #pragma unroll
            for (int tp = 0; tp < 4; tp++) {
                uint32_t bfr[4];
                LDMX4(bfr, sbB + bm_off + tp*(16*80) + 32);
                #pragma unroll
                for (int q = 0; q < 2; q++) {
                    int nt = tp*2 + q;
                    #pragma unroll
                    for (int mt = 0; mt < 4; mt++)
                        MMA16816(acc[mt][nt], ah[mt], bfr[2*q], bfr[2*q+1]);
                }
            }
        }
        if (prep) combine_sts(1, cd1, abuf_n);
        if (c + 3 < NCH) loadB(c + 3, (c + 3) & 3);
    }

    // epilogue: bias + relu, NCHW stores
    #pragma unroll
    for (int mt = 0; mt < 4; mt++) {
        int mA = m0 + warpM*64 + mt*16 + (lid >> 2);
        int mB = mA + 8;
        int bA = mA >> 12, bB = mB >> 12;
        int pA = mA & 4095, pB = mB & 4095;
        #pragma unroll
        for (int nt = 0; nt < 8; nt++) {
            int o = warpN*64 + nt*8 + (lid & 3)*2;
            float bv0 = g_bias2[o], bv1 = g_bias2[o + 1];
            float* d = acc[mt][nt];
            out[((size_t)bA << 20) + ((size_t)o << 12)     + pA] = fmaxf(d[0] + bv0, 0.f);
            out[((size_t)bA << 20) + ((size_t)(o+1) << 12) + pA] = fmaxf(d[1] + bv1, 0.f);
            out[((size_t)bB << 20) + ((size_t)o << 12)     + pB] = fmaxf(d[2] + bv0, 0.f);
            out[((size_t)bB << 20) + ((size_t)(o+1) << 12) + pB] = fmaxf(d[3] + bv1, 0.f);
        }
    }
}

// ---------------- launch ----------------
extern "C" void kernel_launch(void* const* d_in, const int* in_sizes, int n_in,
                              void* d_out, int out_size) {
    const float* input  = (const float*)d_in[0];
    const float* w_off  = (const float*)d_in[1];
    const float* b_off  = (const float*)d_in[2];
    const float* weight = (const float*)d_in[3];
    const float* bias   = (const float*)d_in[4];
    const float* gamma  = (const float*)d_in[5];
    const float* beta   = (const float*)d_in[6];
    const float* mean   = (const float*)d_in[7];
    const float* var    = (const float*)d_in[8];
    float* out = (float*)d_out;

    cudaFuncSetAttribute(k_fused_all, cudaFuncAttributeMaxDynamicSharedMemorySize, SMEMSZ);

    k_transpose_prep<<<dim3(2, 6, 256), dim3(32, 8)>>>(input, weight, w_off, bias, gamma, beta, mean, var);
    k_fused_all<<<Md/128, 256, SMEMSZ>>>(out, b_off);
}